// round 3
// baseline (speedup 1.0000x reference)
#include <cuda_runtime.h>
#include <cstdint>

// Inputs (metadata order):
//   0 origins    [N,3] f32
//   1 directions [N,3] f32
//   2 center     [3]   f32
//   3 radius     [1]   f32
//   4 W1         [3,128] f32
//   5 b1         [128]   f32
//   6 W2         [128,3] f32
//   7 b2         [3]     f32
// Output: color [N,3] f32

#define MAX_ITERS 64
#define NPAIR 64          // 128 hidden units as 64 f32x2 pairs
#define TPB 256

typedef unsigned long long ull;

static __device__ __forceinline__ ull pack2(float lo, float hi) {
    ull d;
    asm("mov.b64 %0, {%1, %2};" : "=l"(d)
        : "r"(__float_as_uint(lo)), "r"(__float_as_uint(hi)));
    return d;
}
static __device__ __forceinline__ void unpack2(ull v, float& lo, float& hi) {
    unsigned a, b;
    asm("mov.b64 {%0, %1}, %2;" : "=r"(a), "=r"(b) : "l"(v));
    lo = __uint_as_float(a);
    hi = __uint_as_float(b);
}
// Packed dual-fp32 FMA (Blackwell f32x2 pipe; ptxas never emits this from C++)
static __device__ __forceinline__ ull ffma2(ull a, ull b, ull c) {
    ull d;
    asm("fma.rn.f32x2 %0, %1, %2, %3;" : "=l"(d) : "l"(a), "l"(b), "l"(c));
    return d;
}

__global__ __launch_bounds__(TPB)
void sphere_trace_mlp_kernel(
    const float* __restrict__ origins,
    const float* __restrict__ dirs,
    const float* __restrict__ center,
    const float* __restrict__ radius,
    const float* __restrict__ W1,   // [3,128] row-major
    const float* __restrict__ b1,   // [128]
    const float* __restrict__ W2,   // [128,3] row-major
    const float* __restrict__ b2,   // [3]
    float* __restrict__ out,        // [N,3]
    int n)
{
    // Shared weights, pre-packed for f32x2 consumption.
    // Pair p covers hidden units j=2p, j+1=2p+1.
    __shared__ float4 sA[NPAIR];  // {W1[0][j], W1[0][j+1], W1[1][j], W1[1][j+1]}
    __shared__ float4 sB[NPAIR];  // {W1[2][j], W1[2][j+1], b1[j],    b1[j+1]}
    __shared__ float4 sC[NPAIR];  // {W2[j][0], W2[j+1][0], W2[j][1], W2[j+1][1]}
    __shared__ float2 sD[NPAIR];  // {W2[j][2], W2[j+1][2]}

    const int tid = threadIdx.x;
    if (tid < NPAIR) {
        const int j = 2 * tid;
        sA[tid] = make_float4(W1[j],       W1[j + 1],
                              W1[128 + j], W1[128 + j + 1]);
        sB[tid] = make_float4(W1[256 + j], W1[256 + j + 1],
                              b1[j],       b1[j + 1]);
        sC[tid] = make_float4(W2[3 * j],     W2[3 * j + 3],
                              W2[3 * j + 1], W2[3 * j + 4]);
        sD[tid] = make_float2(W2[3 * j + 2], W2[3 * j + 5]);
    }

    const int gid = blockIdx.x * TPB + tid;
    const int i = (gid < n) ? gid : (n - 1);   // inert clamp for tail lanes

    const float cx = center[0], cy = center[1], cz = center[2];
    const float r  = radius[0];

    float px = origins[3 * i],  py = origins[3 * i + 1],  pz = origins[3 * i + 2];
    const float dx = dirs[3 * i], dy = dirs[3 * i + 1], dz = dirs[3 * i + 2];

    // ---- Sphere tracing with warp-uniform early exit ----
    // Reference loop: s = sdf(p); p += s*d;  (64x). mask = (last s) < 1e-4.
    // Hit rays: s monotone decreasing -> exiting at s<1e-7 implies ref s64<eps,
    //           remaining point motion < 64*1e-7 (negligible for the color).
    // Miss rays: past closest approach s is monotone increasing -> exiting at
    //           (s>s_prev && s>2e-4) implies ref s64>eps -> color is zeroed,
    //           so the (diverging) point no longer matters.
    float s = 0.0f, s_prev = 3.4e38f;
    #pragma unroll 1
    for (int it = 0; it < MAX_ITERS; ++it) {
        const float ux = px - cx, uy = py - cy, uz = pz - cz;
        s = sqrtf(fmaf(ux, ux, fmaf(uy, uy, uz * uz))) - r;
        const bool done = (s < 1e-7f) || (s > s_prev && s > 2e-4f);
        if (__all_sync(0xffffffffu, done)) break;
        px = fmaf(s, dx, px);
        py = fmaf(s, dy, py);
        pz = fmaf(s, dz, pz);
        s_prev = s;
    }
    const bool hit = (s < 1e-4f);

    __syncthreads();   // shared weights ready

    float c0 = 0.0f, c1 = 0.0f, c2 = 0.0f;

    if (__any_sync(0xffffffffu, hit)) {
        // ---- MLP: h = relu(p@W1 + b1); col = sigmoid(h@W2 + b2) ----
        // Two hidden units per step via f32x2: 6 FFMA2 (fma pipe) +
        // 2 FMNMX (alu pipe) + 4 broadcast LDS per pair.
        const ull px2 = pack2(px, px);
        const ull py2 = pack2(py, py);
        const ull pz2 = pack2(pz, pz);

        ull a0 = 0ull, a1 = 0ull, a2 = 0ull;  // packed (0.f, 0.f)

        const ulonglong2* __restrict__ Au = (const ulonglong2*)sA;
        const ulonglong2* __restrict__ Bu = (const ulonglong2*)sB;
        const ulonglong2* __restrict__ Cu = (const ulonglong2*)sC;
        const ull*        __restrict__ Du = (const ull*)sD;

        #pragma unroll 8
        for (int p = 0; p < NPAIR; ++p) {
            const ulonglong2 wa = Au[p];   // x-pair, y-pair
            const ulonglong2 wb = Bu[p];   // z-pair, bias-pair
            ull h = wb.y;
            h = ffma2(px2, wa.x, h);
            h = ffma2(py2, wa.y, h);
            h = ffma2(pz2, wb.x, h);
            float hl, hh;
            unpack2(h, hl, hh);
            hl = fmaxf(hl, 0.0f);          // relu on the alu pipe
            hh = fmaxf(hh, 0.0f);
            h = pack2(hl, hh);
            const ulonglong2 wc = Cu[p];   // W2 col0-pair, col1-pair
            const ull wd = Du[p];          // W2 col2-pair
            a0 = ffma2(h, wc.x, a0);
            a1 = ffma2(h, wc.y, a1);
            a2 = ffma2(h, wd,   a2);
        }

        float l0, h0, l1, h1, l2, h2;
        unpack2(a0, l0, h0);
        unpack2(a1, l1, h1);
        unpack2(a2, l2, h2);
        const float z0 = b2[0] + l0 + h0;
        const float z1 = b2[1] + l1 + h1;
        const float z2 = b2[2] + l2 + h2;

        c0 = __fdividef(1.0f, 1.0f + __expf(-z0));
        c1 = __fdividef(1.0f, 1.0f + __expf(-z1));
        c2 = __fdividef(1.0f, 1.0f + __expf(-z2));
    }

    if (gid < n) {
        out[3 * gid]     = hit ? c0 : 0.0f;
        out[3 * gid + 1] = hit ? c1 : 0.0f;
        out[3 * gid + 2] = hit ? c2 : 0.0f;
    }
}

extern "C" void kernel_launch(void* const* d_in, const int* in_sizes, int n_in,
                              void* d_out, int out_size) {
    const float* origins = (const float*)d_in[0];
    const float* dirs    = (const float*)d_in[1];
    const float* center  = (const float*)d_in[2];
    const float* radius  = (const float*)d_in[3];
    const float* W1      = (const float*)d_in[4];
    const float* b1      = (const float*)d_in[5];
    const float* W2      = (const float*)d_in[6];
    const float* b2      = (const float*)d_in[7];
    float* out = (float*)d_out;

    const int n = in_sizes[0] / 3;
    const int blocks = (n + TPB - 1) / TPB;
    sphere_trace_mlp_kernel<<<blocks, TPB>>>(origins, dirs, center, radius,
                                             W1, b1, W2, b2, out, n);
}

// round 4
// speedup vs baseline: 1.0959x; 1.0959x over previous
#include <cuda_runtime.h>
#include <cstdint>

// Inputs (metadata order):
//   0 origins    [N,3] f32
//   1 directions [N,3] f32
//   2 center     [3]   f32
//   3 radius     [1]   f32
//   4 W1         [3,128] f32
//   5 b1         [128]   f32
//   6 W2         [128,3] f32
//   7 b2         [3]     f32
// Output: color [N,3] f32

#define MAX_ITERS 64
#define NPAIR 64          // 128 hidden units as 64 f32x2 pairs
#define TPB 256
#define RPT 4             // rays per thread: amortizes shared weight LDS 4x

typedef unsigned long long ull;

static __device__ __forceinline__ ull pack2(float lo, float hi) {
    ull d;
    asm("mov.b64 %0, {%1, %2};" : "=l"(d)
        : "r"(__float_as_uint(lo)), "r"(__float_as_uint(hi)));
    return d;
}
static __device__ __forceinline__ void unpack2(ull v, float& lo, float& hi) {
    unsigned a, b;
    asm("mov.b64 {%0, %1}, %2;" : "=r"(a), "=r"(b) : "l"(v));
    lo = __uint_as_float(a);
    hi = __uint_as_float(b);
}
// Packed dual-fp32 FMA (Blackwell f32x2 pipe; ptxas never emits this from C++)
static __device__ __forceinline__ ull ffma2(ull a, ull b, ull c) {
    ull d;
    asm("fma.rn.f32x2 %0, %1, %2, %3;" : "=l"(d) : "l"(a), "l"(b), "l"(c));
    return d;
}

__global__ __launch_bounds__(TPB)
void sphere_trace_mlp_kernel(
    const float* __restrict__ origins,
    const float* __restrict__ dirs,
    const float* __restrict__ center,
    const float* __restrict__ radius,
    const float* __restrict__ W1,   // [3,128] row-major
    const float* __restrict__ b1,   // [128]
    const float* __restrict__ W2,   // [128,3] row-major
    const float* __restrict__ b2,   // [3]
    float* __restrict__ out,        // [N,3]
    int n)
{
    // Shared weights, pre-packed for f32x2 consumption.
    // Pair p covers hidden units j=2p, j+1=2p+1.
    __shared__ float4 sA[NPAIR];  // {W1[0][j], W1[0][j+1], W1[1][j], W1[1][j+1]}
    __shared__ float4 sB[NPAIR];  // {W1[2][j], W1[2][j+1], b1[j],    b1[j+1]}
    __shared__ float4 sC[NPAIR];  // {W2[j][0], W2[j+1][0], W2[j][1], W2[j+1][1]}
    __shared__ float2 sD[NPAIR];  // {W2[j][2], W2[j+1][2]}

    const int tid = threadIdx.x;
    if (tid < NPAIR) {
        const int j = 2 * tid;
        sA[tid] = make_float4(W1[j],       W1[j + 1],
                              W1[128 + j], W1[128 + j + 1]);
        sB[tid] = make_float4(W1[256 + j], W1[256 + j + 1],
                              b1[j],       b1[j + 1]);
        sC[tid] = make_float4(W2[3 * j],     W2[3 * j + 3],
                              W2[3 * j + 1], W2[3 * j + 4]);
        sD[tid] = make_float2(W2[3 * j + 2], W2[3 * j + 5]);
    }

    const int base = blockIdx.x * (TPB * RPT) + tid;

    const float cx = center[0], cy = center[1], cz = center[2];
    const float r  = radius[0];

    int   idx[RPT];
    float px[RPT], py[RPT], pz[RPT];
    float dx[RPT], dy[RPT], dz[RPT];
    float s[RPT], sp[RPT];
    bool  dn[RPT];

    #pragma unroll
    for (int k = 0; k < RPT; ++k) {
        const int g = base + k * TPB;         // coalesced per-k
        idx[k] = g;
        const int i = (g < n) ? g : (n - 1);  // inert clamp for tail
        px[k] = origins[3 * i];  py[k] = origins[3 * i + 1];  pz[k] = origins[3 * i + 2];
        dx[k] = dirs[3 * i];     dy[k] = dirs[3 * i + 1];     dz[k] = dirs[3 * i + 2];
        s[k] = 0.0f; sp[k] = 3.4e38f; dn[k] = false;
    }

    // ---- Sphere tracing with warp-uniform early exit ----
    // Reference loop: s = sdf(p); p += s*d;  (64x). mask = (last s) < 1e-4.
    // Hit rays: s monotone decreasing -> exiting at s<1e-7 implies ref s64<eps,
    //           residual point motion < 64*1e-7 (negligible for the color).
    // Miss rays: past closest approach s is monotone increasing -> exiting at
    //           (s>s_prev && s>2e-4) implies ref s64>eps -> color is zeroed.
    #pragma unroll 1
    for (int it = 0; it < MAX_ITERS; ++it) {
        bool all_done = true;
        #pragma unroll
        for (int k = 0; k < RPT; ++k) {
            const float ux = px[k] - cx, uy = py[k] - cy, uz = pz[k] - cz;
            s[k] = sqrtf(fmaf(ux, ux, fmaf(uy, uy, uz * uz))) - r;
            dn[k] = (s[k] < 1e-7f) || (s[k] > sp[k] && s[k] > 2e-4f);
            all_done &= dn[k];
        }
        if (__all_sync(0xffffffffu, all_done)) break;
        #pragma unroll
        for (int k = 0; k < RPT; ++k) {
            px[k] = fmaf(s[k], dx[k], px[k]);
            py[k] = fmaf(s[k], dy[k], py[k]);
            pz[k] = fmaf(s[k], dz[k], pz[k]);
            sp[k] = s[k];
        }
    }

    bool hit[RPT];
    bool any_hit = false;
    #pragma unroll
    for (int k = 0; k < RPT; ++k) {
        hit[k] = (s[k] < 1e-4f);
        any_hit |= hit[k];
    }

    __syncthreads();   // shared weights ready

    float c0[RPT], c1[RPT], c2[RPT];
    #pragma unroll
    for (int k = 0; k < RPT; ++k) { c0[k] = 0.f; c1[k] = 0.f; c2[k] = 0.f; }

    if (__any_sync(0xffffffffu, any_hit)) {
        // ---- MLP: h = relu(p@W1 + b1); col = sigmoid(h@W2 + b2) ----
        // 4 shared loads per pair now feed RPT rays: 24 FFMA2 + 8 FMNMX
        // per pair per thread, LDS per ray cut 4x vs round-3 kernel.
        ull px2[RPT], py2[RPT], pz2[RPT];
        ull a0[RPT], a1[RPT], a2[RPT];
        #pragma unroll
        for (int k = 0; k < RPT; ++k) {
            px2[k] = pack2(px[k], px[k]);
            py2[k] = pack2(py[k], py[k]);
            pz2[k] = pack2(pz[k], pz[k]);
            a0[k] = 0ull; a1[k] = 0ull; a2[k] = 0ull;
        }

        const ulonglong2* __restrict__ Au = (const ulonglong2*)sA;
        const ulonglong2* __restrict__ Bu = (const ulonglong2*)sB;
        const ulonglong2* __restrict__ Cu = (const ulonglong2*)sC;
        const ull*        __restrict__ Du = (const ull*)sD;

        #pragma unroll 4
        for (int p = 0; p < NPAIR; ++p) {
            const ulonglong2 wa = Au[p];   // x-pair, y-pair
            const ulonglong2 wb = Bu[p];   // z-pair, bias-pair
            const ulonglong2 wc = Cu[p];   // W2 col0-pair, col1-pair
            const ull wd = Du[p];          // W2 col2-pair
            #pragma unroll
            for (int k = 0; k < RPT; ++k) {
                ull h = wb.y;
                h = ffma2(px2[k], wa.x, h);
                h = ffma2(py2[k], wa.y, h);
                h = ffma2(pz2[k], wb.x, h);
                float hl, hh;
                unpack2(h, hl, hh);
                hl = fmaxf(hl, 0.0f);      // relu on the alu pipe
                hh = fmaxf(hh, 0.0f);
                h = pack2(hl, hh);
                a0[k] = ffma2(h, wc.x, a0[k]);
                a1[k] = ffma2(h, wc.y, a1[k]);
                a2[k] = ffma2(h, wd,   a2[k]);
            }
        }

        const float bb0 = b2[0], bb1 = b2[1], bb2 = b2[2];
        #pragma unroll
        for (int k = 0; k < RPT; ++k) {
            float l0, h0, l1, h1, l2, h2;
            unpack2(a0[k], l0, h0);
            unpack2(a1[k], l1, h1);
            unpack2(a2[k], l2, h2);
            const float z0 = bb0 + l0 + h0;
            const float z1 = bb1 + l1 + h1;
            const float z2 = bb2 + l2 + h2;
            c0[k] = __fdividef(1.0f, 1.0f + __expf(-z0));
            c1[k] = __fdividef(1.0f, 1.0f + __expf(-z1));
            c2[k] = __fdividef(1.0f, 1.0f + __expf(-z2));
        }
    }

    #pragma unroll
    for (int k = 0; k < RPT; ++k) {
        const int g = idx[k];
        if (g < n) {
            out[3 * g]     = hit[k] ? c0[k] : 0.0f;
            out[3 * g + 1] = hit[k] ? c1[k] : 0.0f;
            out[3 * g + 2] = hit[k] ? c2[k] : 0.0f;
        }
    }
}

extern "C" void kernel_launch(void* const* d_in, const int* in_sizes, int n_in,
                              void* d_out, int out_size) {
    const float* origins = (const float*)d_in[0];
    const float* dirs    = (const float*)d_in[1];
    const float* center  = (const float*)d_in[2];
    const float* radius  = (const float*)d_in[3];
    const float* W1      = (const float*)d_in[4];
    const float* b1      = (const float*)d_in[5];
    const float* W2      = (const float*)d_in[6];
    const float* b2      = (const float*)d_in[7];
    float* out = (float*)d_out;

    const int n = in_sizes[0] / 3;
    const int per_block = TPB * RPT;
    const int blocks = (n + per_block - 1) / per_block;
    sphere_trace_mlp_kernel<<<blocks, TPB>>>(origins, dirs, center, radius,
                                             W1, b1, W2, b2, out, n);
}

// round 6
// speedup vs baseline: 1.4249x; 1.3003x over previous
#include <cuda_runtime.h>
#include <cstdint>

// Inputs (metadata order):
//   0 origins [N,3] f32   1 directions [N,3] f32   2 center [3] f32
//   3 radius  [1]  f32    4 W1 [3,128] f32         5 b1 [128] f32
//   6 W2 [128,3] f32      7 b2 [3] f32
// Output: color [N,3] f32

#define MAX_ITERS 64
#define NPAIR 64          // 128 hidden units as 64 f32x2 pairs
#define TPB 256
#define RPT 4             // rays per thread

typedef unsigned long long ull;

static __device__ __forceinline__ ull pack2(float lo, float hi) {
    ull d;
    asm("mov.b64 %0, {%1, %2};" : "=l"(d)
        : "r"(__float_as_uint(lo)), "r"(__float_as_uint(hi)));
    return d;
}
static __device__ __forceinline__ void unpack2(ull v, float& lo, float& hi) {
    unsigned a, b;
    asm("mov.b64 {%0, %1}, %2;" : "=r"(a), "=r"(b) : "l"(v));
    lo = __uint_as_float(a);
    hi = __uint_as_float(b);
}
// Packed dual-fp32 FMA (Blackwell f32x2 pipe; ptxas never emits this from C++)
static __device__ __forceinline__ ull ffma2(ull a, ull b, ull c) {
    ull d;
    asm("fma.rn.f32x2 %0, %1, %2, %3;" : "=l"(d) : "l"(a), "l"(b), "l"(c));
    return d;
}
// Single-MUFU sqrt (rel err ~3.4e-7; thresholds have >100x margin)
static __device__ __forceinline__ float fsqrt_fast(float x) {
    float y;
    asm("sqrt.approx.f32 %0, %1;" : "=f"(y) : "f"(x));
    return y;
}

__global__ __launch_bounds__(TPB)
void sphere_trace_mlp_kernel(
    const float* __restrict__ origins,
    const float* __restrict__ dirs,
    const float* __restrict__ center,
    const float* __restrict__ radius,
    const float* __restrict__ W1,   // [3,128] row-major
    const float* __restrict__ b1,   // [128]
    const float* __restrict__ W2,   // [128,3] row-major
    const float* __restrict__ b2,   // [3]
    float* __restrict__ out,        // [N,3]
    int n)
{
    // Shared weights, pre-packed for f32x2 consumption. Pair p = units (2p, 2p+1).
    __shared__ float4 sA[NPAIR];  // {W1[0][j], W1[0][j+1], W1[1][j], W1[1][j+1]}
    __shared__ float4 sB[NPAIR];  // {W1[2][j], W1[2][j+1], b1[j],    b1[j+1]}
    __shared__ float4 sC[NPAIR];  // {W2[j][0], W2[j+1][0], W2[j][1], W2[j+1][1]}
    __shared__ float2 sD[NPAIR];  // {W2[j][2], W2[j+1][2]}

    const int tid = threadIdx.x;
    if (tid < NPAIR) {
        const int j = 2 * tid;
        sA[tid] = make_float4(W1[j],       W1[j + 1],
                              W1[128 + j], W1[128 + j + 1]);
        sB[tid] = make_float4(W1[256 + j], W1[256 + j + 1],
                              b1[j],       b1[j + 1]);
        sC[tid] = make_float4(W2[3 * j],     W2[3 * j + 3],
                              W2[3 * j + 1], W2[3 * j + 4]);
        sD[tid] = make_float2(W2[3 * j + 2], W2[3 * j + 5]);
    }

    const int base = blockIdx.x * (TPB * RPT) + tid;

    const float cx = center[0], cy = center[1], cz = center[2];
    const float r  = radius[0];

    int   idx[RPT];
    float ux[RPT], uy[RPT], uz[RPT];      // u = p - c (tracked directly)
    float dx[RPT], dy[RPT], dz[RPT];
    float s[RPT], sp[RPT];

    #pragma unroll
    for (int k = 0; k < RPT; ++k) {
        const int g = base + k * TPB;         // coalesced per-k
        idx[k] = g;
        const int i = (g < n) ? g : (n - 1);  // inert clamp for tail
        ux[k] = origins[3 * i]     - cx;
        uy[k] = origins[3 * i + 1] - cy;
        uz[k] = origins[3 * i + 2] - cz;
        dx[k] = dirs[3 * i]; dy[k] = dirs[3 * i + 1]; dz[k] = dirs[3 * i + 2];
        s[k] = 0.0f; sp[k] = 3.4e38f;
    }

    // ---- Sphere tracing, always-update, exit check every 2 steps ----
    // Reference: 64x { s = sdf(p); p += s*d }  mask = (last s) < 1e-4.
    // Hit rays: s monotone decreasing; once s<1e-7, further updates move p by
    //   <64e-7 and ref s64<eps -> identical mask/color.
    // Miss rays: past closest approach s monotone increasing; once
    //   (s>s_prev && s>2e-4), ref s64>eps -> color is zeroed anyway.
    // Overshooting the exit by <=2 steps is harmless under both monotonicities.
    #pragma unroll 1
    for (int it2 = 0; it2 < MAX_ITERS / 2; ++it2) {
        #pragma unroll
        for (int k = 0; k < RPT; ++k) {      // step A
            const float q = fmaf(ux[k], ux[k], fmaf(uy[k], uy[k], uz[k] * uz[k]));
            const float sa = fsqrt_fast(q) - r;
            ux[k] = fmaf(sa, dx[k], ux[k]);
            uy[k] = fmaf(sa, dy[k], uy[k]);
            uz[k] = fmaf(sa, dz[k], uz[k]);
            sp[k] = sa;
        }
        bool all_done = true;
        #pragma unroll
        for (int k = 0; k < RPT; ++k) {      // step B + check
            const float q = fmaf(ux[k], ux[k], fmaf(uy[k], uy[k], uz[k] * uz[k]));
            const float sb = fsqrt_fast(q) - r;
            ux[k] = fmaf(sb, dx[k], ux[k]);
            uy[k] = fmaf(sb, dy[k], uy[k]);
            uz[k] = fmaf(sb, dz[k], uz[k]);
            s[k] = sb;
            const bool done = (sb < 1e-7f) || (sb > sp[k] && sb > 2e-4f);
            all_done &= done;
        }
        if (__all_sync(0xffffffffu, all_done)) break;
    }

    bool hit[RPT];
    #pragma unroll
    for (int k = 0; k < RPT; ++k) hit[k] = (s[k] < 1e-4f);

    __syncthreads();   // shared weights ready

    // ---- MLP: h = relu(p@W1 + b1); col = sigmoid(h@W2 + b2) ----
    // p = u + c. 4 broadcast LDS per pair feed RPT rays:
    // 24 FFMA2 (fma pipe) + 8 FMNMX (alu pipe) per pair per thread.
    ull px2[RPT], py2[RPT], pz2[RPT];
    ull a0[RPT], a1[RPT], a2[RPT];
    #pragma unroll
    for (int k = 0; k < RPT; ++k) {
        const float px = ux[k] + cx, py = uy[k] + cy, pz = uz[k] + cz;
        px2[k] = pack2(px, px);
        py2[k] = pack2(py, py);
        pz2[k] = pack2(pz, pz);
        a0[k] = 0ull; a1[k] = 0ull; a2[k] = 0ull;
    }

    const ulonglong2* __restrict__ Au = (const ulonglong2*)sA;
    const ulonglong2* __restrict__ Bu = (const ulonglong2*)sB;
    const ulonglong2* __restrict__ Cu = (const ulonglong2*)sC;
    const ull*        __restrict__ Du = (const ull*)sD;

    #pragma unroll 4
    for (int p = 0; p < NPAIR; ++p) {
        const ulonglong2 wa = Au[p];   // x-pair, y-pair
        const ulonglong2 wb = Bu[p];   // z-pair, bias-pair
        const ulonglong2 wc = Cu[p];   // W2 col0-pair, col1-pair
        const ull wd = Du[p];          // W2 col2-pair
        #pragma unroll
        for (int k = 0; k < RPT; ++k) {
            ull h = wb.y;
            h = ffma2(px2[k], wa.x, h);
            h = ffma2(py2[k], wa.y, h);
            h = ffma2(pz2[k], wb.x, h);
            float hl, hh;
            unpack2(h, hl, hh);
            hl = fmaxf(hl, 0.0f);      // relu on the alu pipe
            hh = fmaxf(hh, 0.0f);
            h = pack2(hl, hh);
            a0[k] = ffma2(h, wc.x, a0[k]);
            a1[k] = ffma2(h, wc.y, a1[k]);
            a2[k] = ffma2(h, wd,   a2[k]);
        }
    }

    const float bb0 = b2[0], bb1 = b2[1], bb2 = b2[2];
    #pragma unroll
    for (int k = 0; k < RPT; ++k) {
        float l0, h0, l1, h1, l2, h2;
        unpack2(a0[k], l0, h0);
        unpack2(a1[k], l1, h1);
        unpack2(a2[k], l2, h2);
        const float z0 = bb0 + l0 + h0;
        const float z1 = bb1 + l1 + h1;
        const float z2 = bb2 + l2 + h2;
        const float c0 = __fdividef(1.0f, 1.0f + __expf(-z0));
        const float c1 = __fdividef(1.0f, 1.0f + __expf(-z1));
        const float c2 = __fdividef(1.0f, 1.0f + __expf(-z2));
        const int g = idx[k];
        if (g < n) {
            out[3 * g]     = hit[k] ? c0 : 0.0f;
            out[3 * g + 1] = hit[k] ? c1 : 0.0f;
            out[3 * g + 2] = hit[k] ? c2 : 0.0f;
        }
    }
}

extern "C" void kernel_launch(void* const* d_in, const int* in_sizes, int n_in,
                              void* d_out, int out_size) {
    const float* origins = (const float*)d_in[0];
    const float* dirs    = (const float*)d_in[1];
    const float* center  = (const float*)d_in[2];
    const float* radius  = (const float*)d_in[3];
    const float* W1      = (const float*)d_in[4];
    const float* b1      = (const float*)d_in[5];
    const float* W2      = (const float*)d_in[6];
    const float* b2      = (const float*)d_in[7];
    float* out = (float*)d_out;

    const int n = in_sizes[0] / 3;
    const int per_block = TPB * RPT;
    const int blocks = (n + per_block - 1) / per_block;
    sphere_trace_mlp_kernel<<<blocks, TPB>>>(origins, dirs, center, radius,
                                             W1, b1, W2, b2, out, n);
}